// round 12
// baseline (speedup 1.0000x reference)
#include <cuda_runtime.h>
#include <cuda_fp16.h>
#include <cstdint>

// ============================ problem constants ============================
#define BH   128
#define SEQ  1024
#define DIM  64
#define QT   128         // q rows per CTA (4 warps x 32 rows)
#define KT   128
#define NIT  8
#define NTHR 128
// fold 1/sqrt(64) * log2(e) into Q so scores are in log2 domain
#define QSCALE 0.1803368801111244f

// ============================ device scratch ============================
__device__ __half g_Kh[BH * SEQ * DIM];   // K, fp16
__device__ __half g_Lh[BH * SEQ * DIM];   // log_sigmoid(V), fp16
// permuted mask bits: [b][row][it][quad] u32; bit(2i+z) = mask[b][row][it*128 + i*8 + 2*quad + z]
__device__ unsigned g_Mp[8 * SEQ * NIT * 4];

// ============================ PTX helpers ============================
__device__ __forceinline__ uint32_t smem_u32(const void* p) {
    uint32_t a;
    asm("{ .reg .u64 t; cvta.to.shared.u64 t, %1; cvt.u32.u64 %0, t; }"
        : "=r"(a) : "l"(p));
    return a;
}
__device__ __forceinline__ uint32_t swz(uint32_t o) { return o ^ ((o >> 3) & 0x70); }

__device__ __forceinline__ void ldmx4(uint32_t& r0, uint32_t& r1, uint32_t& r2,
                                      uint32_t& r3, uint32_t a) {
    asm volatile("ldmatrix.sync.aligned.m8n8.x4.shared.b16 {%0,%1,%2,%3}, [%4];"
        : "=r"(r0), "=r"(r1), "=r"(r2), "=r"(r3) : "r"(a));
}
__device__ __forceinline__ void ldmx4t(uint32_t& r0, uint32_t& r1, uint32_t& r2,
                                       uint32_t& r3, uint32_t a) {
    asm volatile("ldmatrix.sync.aligned.m8n8.x4.trans.shared.b16 {%0,%1,%2,%3}, [%4];"
        : "=r"(r0), "=r"(r1), "=r"(r2), "=r"(r3) : "r"(a));
}
// NON-volatile: pure register op; lets ptxas pipeline ldmatrix over mma groups
__device__ __forceinline__ void mma_f16(float* c, const uint32_t* a,
                                        uint32_t b0, uint32_t b1) {
    asm("mma.sync.aligned.m16n8k16.row.col.f32.f16.f16.f32 "
        "{%0,%1,%2,%3}, {%4,%5,%6,%7}, {%8,%9}, {%0,%1,%2,%3};"
        : "+f"(c[0]), "+f"(c[1]), "+f"(c[2]), "+f"(c[3])
        : "r"(a[0]), "r"(a[1]), "r"(a[2]), "r"(a[3]), "r"(b0), "r"(b1));
}
__device__ __forceinline__ uint32_t pack_h2(float lo, float hi) {
    uint32_t r;
    asm("cvt.rn.f16x2.f32 %0, %1, %2;" : "=r"(r) : "f"(hi), "f"(lo));
    return r;
}
__device__ __forceinline__ float ex2(float x) {
    float r;
    asm("ex2.approx.ftz.f32 %0, %1;" : "=f"(r) : "f"(x));
    return r;
}
__device__ __forceinline__ void cp16(uint32_t s, const void* g) {
    asm volatile("cp.async.cg.shared.global [%0], [%1], 16;" :: "r"(s), "l"(g));
}
#define CP_COMMIT() asm volatile("cp.async.commit_group;" ::: "memory")
#define CP_WAIT(n)  asm volatile("cp.async.wait_group %0;" :: "n"(n) : "memory")

// ============================ fused preprocessing ============================
// blocks [0, 1024): mask bit-permute, one thread per output word (quad).
// blocks [1024, 9216): K -> fp16, log_sigmoid(V) -> fp16.
#define MASK_BLOCKS 1024
__global__ void prep_all(const void* __restrict__ msrc,
                         const float4* __restrict__ K,
                         const float4* __restrict__ V) {
    if (blockIdx.x < MASK_BLOCKS) {
        int idx = blockIdx.x * 256 + threadIdx.x;   // 262144 words
        int q = idx & 3;
        int chunk = idx >> 2;                        // 65536 chunks of 128 elems
        size_t ebase = (size_t)chunk * 128;          // element index
        uint4 d = ((const uint4*)msrc)[ebase / 16 + q];
        int ok = (d.x==0u||d.x==1u||d.x==0x3F800000u) && (d.y==0u||d.y==1u||d.y==0x3F800000u)
              && (d.z==0u||d.z==1u||d.z==0x3F800000u) && (d.w==0u||d.w==1u||d.w==0x3F800000u);
        int wide = __syncthreads_and(ok);
        unsigned w = 0;
        if (wide) {
            const uint2* s = (const uint2*)msrc + ebase / 2 + q;
#pragma unroll
            for (int i = 0; i < 16; i++) {
                uint2 a = s[i * 4];
                w |= ((a.x ? 1u : 0u) << (2 * i)) | ((a.y ? 1u : 0u) << (2 * i + 1));
            }
        } else {
            const unsigned short* s = (const unsigned short*)msrc + ebase / 2 + q;
#pragma unroll
            for (int i = 0; i < 16; i++) {
                unsigned v = s[i * 4];
                w |= (((v & 0xffu) ? 1u : 0u) << (2 * i)) | (((v >> 8) ? 1u : 0u) << (2 * i + 1));
            }
        }
        g_Mp[(size_t)chunk * 4 + q] = w;
    } else {
        int i = (blockIdx.x - MASK_BLOCKS) * 256 + threadIdx.x;
        float4 k = K[i];
        __half2* ko = (__half2*)g_Kh;
        ko[2 * i]     = __floats2half2_rn(k.x, k.y);
        ko[2 * i + 1] = __floats2half2_rn(k.z, k.w);
        float4 v = V[i];
        float a0 = fminf(v.x, 0.f) - log1pf(__expf(-fabsf(v.x)));
        float a1 = fminf(v.y, 0.f) - log1pf(__expf(-fabsf(v.y)));
        float a2 = fminf(v.z, 0.f) - log1pf(__expf(-fabsf(v.z)));
        float a3 = fminf(v.w, 0.f) - log1pf(__expf(-fabsf(v.w)));
        __half2* lo = (__half2*)g_Lh;
        lo[2 * i]     = __floats2half2_rn(a0, a1);
        lo[2 * i + 1] = __floats2half2_rn(a2, a3);
    }
}

// ============================ attention kernel ============================
// smem: 2 stages x (K tile 16KB + L tile 16KB) = 64KB; rows 128B, SW128 swizzle
#define ST_K(s) ((s) * 32768)
#define ST_L(s) ((s) * 32768 + 16384)
#define SMEM_BYTES 65536

__device__ __forceinline__ void prefetch_tiles(int st, int t,
                                               const __half* Kb, const __half* Lb,
                                               int k0, uint32_t sb) {
#pragma unroll
    for (int i = t; i < 1024; i += NTHR) {
        int r = i >> 3, j = i & 7;
        cp16(sb + ST_K(st) + swz(r * 128 + j * 16), Kb + (size_t)(k0 + r) * DIM + j * 8);
    }
#pragma unroll
    for (int i = t; i < 1024; i += NTHR) {
        int r = i >> 3, j = i & 7;
        cp16(sb + ST_L(st) + swz(r * 128 + j * 16), Lb + (size_t)(k0 + r) * DIM + j * 8);
    }
}

__global__ void __launch_bounds__(NTHR, 2)
attn_kernel(const float* __restrict__ Q, float* __restrict__ out) {
    extern __shared__ char smem[];
    const uint32_t sb = smem_u32(smem);
    const int t = threadIdx.x, w = t >> 5, lane = t & 31;
    const int bh = blockIdx.y, q0 = blockIdx.x * QT;
    const int b = bh >> 4;

    const __half* Kbh = g_Kh + (size_t)bh * SEQ * DIM;
    const __half* Lbh = g_Lh + (size_t)bh * SEQ * DIM;

    // ---- Q tile: fp32 LDG -> fp16 convert (fold scale*log2e) -> smem stage0 ----
    {
        const float4* Qs = (const float4*)(Q + ((size_t)bh * SEQ + q0) * DIM);
#pragma unroll
        for (int i = t; i < 2048; i += NTHR) {   // 128 rows x 16 float4
            int r = i >> 4, j = i & 15;
            float4 q = Qs[i];
            uint2 hv;
            hv.x = pack_h2(q.x * QSCALE, q.y * QSCALE);
            hv.y = pack_h2(q.z * QSCALE, q.w * QSCALE);
            *(uint2*)(smem + ST_K(0) + swz(r * 128 + j * 8)) = hv;
        }
    }
    __syncthreads();

    const uint32_t xr = (uint32_t)(lane & 7) << 4;   // swizzle XOR (row&7)<<4
    // A-fragments: 2 m16 tiles (rows 32w+16m)
    uint32_t qf[2][4][4];
    {
        uint32_t ch = (uint32_t)(lane >> 4) << 4;    // +16B for k8..15 octets
#pragma unroll
        for (int m = 0; m < 2; m++) {
            uint32_t base = sb + ST_K(0) + (uint32_t)(32 * w + 16 * m + (lane & 15)) * 128;
#pragma unroll
            for (int kd = 0; kd < 4; kd++)
                ldmx4(qf[m][kd][0], qf[m][kd][1], qf[m][kd][2], qf[m][kd][3],
                      base + (((uint32_t)kd * 32 + ch) ^ xr));
        }
    }
    __syncthreads();

    // permuted mask words; this thread's quad = lane&3; rows 32w+16m+{0,8}+(lane>>2)
    const unsigned* mpA = g_Mp + ((size_t)(b * 1024 + q0 + 32 * w + (lane >> 2)) * NIT) * 4 + (lane & 3);

    // per-thread ldmatrix base offsets
    const uint32_t rbK = (uint32_t)((lane & 7) + ((lane >> 4) << 3));       // K B-frag rows
    const uint32_t csK = (uint32_t)(((lane >> 3) & 1) << 4);                // K col sel
    const uint32_t rbL = (uint32_t)((lane & 7) + (((lane >> 3) & 1) << 3)); // L rows
    const uint32_t csL = (uint32_t)(((lane >> 4) & 1) << 4);                // L col sel

    float oacc[2][8][4];
#pragma unroll
    for (int m = 0; m < 2; m++)
#pragma unroll
        for (int j = 0; j < 8; j++)
#pragma unroll
            for (int x = 0; x < 4; x++) oacc[m][j][x] = 0.f;
    // den[m][g]: m-tile, row-group (+0 / +8); two partials each to break FADD chain
    float denA[2][2] = {{0.f, 0.f}, {0.f, 0.f}};
    float denB[2][2] = {{0.f, 0.f}, {0.f, 0.f}};

    prefetch_tiles(0, t, Kbh, Lbh, 0, sb);
    CP_COMMIT();

    for (int it = 0; it < NIT; it++) {
        const int st = it & 1;
        if (it < NIT - 1) {
            prefetch_tiles(st ^ 1, t, Kbh, Lbh, (it + 1) * KT, sb);
            CP_COMMIT();
            CP_WAIT(1);
        } else {
            CP_WAIT(0);
        }
        __syncthreads();

        // mask words for 4 row-octets: [m][g] rows 32w+16m+8g
        unsigned mw[2][2];
#pragma unroll
        for (int m = 0; m < 2; m++) {
            mw[m][0] = mpA[(16 * m) * NIT * 4 + it * 4];
            mw[m][1] = mpA[(16 * m + 8) * NIT * 4 + it * 4];
        }
        const uint32_t baseK = sb + ST_K(st) + rbK * 128;
        const uint32_t baseL = sb + ST_L(st) + rbL * 128;

#pragma unroll
        for (int h = 0; h < 2; h++) {            // two 64-col halves
            // ---- GEMM1 half: S[32x64] = Q @ K^T (B frags shared by both m-tiles) ----
            float c[2][8][4];
#pragma unroll
            for (int m = 0; m < 2; m++)
#pragma unroll
                for (int j = 0; j < 8; j++)
#pragma unroll
                    for (int x = 0; x < 4; x++) c[m][j][x] = 0.f;
#pragma unroll
            for (int jp = 0; jp < 4; jp++) {
                const uint32_t ko = (uint32_t)(h * 4 + jp) * 2048;
                uint32_t bfr[4][4];
#pragma unroll
                for (int kd = 0; kd < 4; kd++)
                    ldmx4(bfr[kd][0], bfr[kd][1], bfr[kd][2], bfr[kd][3],
                          baseK + ko + (((uint32_t)kd * 32 + csK) ^ xr));
#pragma unroll
                for (int kd = 0; kd < 4; kd++)
#pragma unroll
                    for (int m = 0; m < 2; m++) {
                        mma_f16(c[m][2 * jp],     qf[m][kd], bfr[kd][0], bfr[kd][1]);
                        mma_f16(c[m][2 * jp + 1], qf[m][kd], bfr[kd][2], bfr[kd][3]);
                    }
            }

            // ---- epilogue half: P = mask * 2^S ----
            uint32_t p2[2][8][2];
#pragma unroll
            for (int m = 0; m < 2; m++) {
                const unsigned ma = mw[m][0] >> (16 * h), mb = mw[m][1] >> (16 * h);
#pragma unroll
                for (int j = 0; j < 8; j++) {
                    unsigned ba = ma >> (2 * j), bb = mb >> (2 * j);
                    float s0 = (ba & 1u) ? c[m][j][0] : -127.f;
                    float s1 = (ba & 2u) ? c[m][j][1] : -127.f;
                    float s2 = (bb & 1u) ? c[m][j][2] : -127.f;
                    float s3 = (bb & 2u) ? c[m][j][3] : -127.f;
                    float e0 = ex2(s0), e1 = ex2(s1);
                    float e2 = ex2(s2), e3 = ex2(s3);
                    if (j & 1) { denB[m][0] += e0 + e1; denB[m][1] += e2 + e3; }
                    else       { denA[m][0] += e0 + e1; denA[m][1] += e2 + e3; }
                    p2[m][j][0] = pack_h2(e0, e1);
                    p2[m][j][1] = pack_h2(e2, e3);
                }
            }

            // ---- GEMM2 half: O[32x64] += P @ L (L frags shared by both m-tiles) ----
#pragma unroll
            for (int kk = 0; kk < 4; kk++) {
                const uint32_t ko = (uint32_t)(h * 4 + kk) * 2048;
                uint32_t bl[4][4];
#pragma unroll
                for (int dp = 0; dp < 4; dp++)
                    ldmx4t(bl[dp][0], bl[dp][1], bl[dp][2], bl[dp][3],
                           baseL + ko + (((uint32_t)dp * 32 + csL) ^ xr));
#pragma unroll
                for (int m = 0; m < 2; m++) {
                    uint32_t a[4] = {p2[m][2 * kk][0], p2[m][2 * kk][1],
                                     p2[m][2 * kk + 1][0], p2[m][2 * kk + 1][1]};
#pragma unroll
                    for (int dp = 0; dp < 4; dp++) {
                        mma_f16(oacc[m][2 * dp],     a, bl[dp][0], bl[dp][1]);
                        mma_f16(oacc[m][2 * dp + 1], a, bl[dp][2], bl[dp][3]);
                    }
                }
            }
        }
        __syncthreads();
    }

    // ---- final: quad-reduce den, normalize, exp, store ----
    const int cb = 2 * (lane & 3);
#pragma unroll
    for (int m = 0; m < 2; m++) {
        float d0 = denA[m][0] + denB[m][0];
        float d1 = denA[m][1] + denB[m][1];
        d0 += __shfl_xor_sync(0xffffffffu, d0, 1);
        d0 += __shfl_xor_sync(0xffffffffu, d0, 2);
        d1 += __shfl_xor_sync(0xffffffffu, d1, 1);
        d1 += __shfl_xor_sync(0xffffffffu, d1, 2);
        const float inv0 = 1.f / d0, inv1 = 1.f / d1;

        const int r0 = q0 + 32 * w + 16 * m + (lane >> 2);
        float* o0 = out + ((size_t)bh * SEQ + r0) * DIM + cb;
        float* o1 = o0 + 8 * DIM;
#pragma unroll
        for (int j = 0; j < 8; j++) {
            float2 v0, v1;
            v0.x = __expf(oacc[m][j][0] * inv0);
            v0.y = __expf(oacc[m][j][1] * inv0);
            v1.x = __expf(oacc[m][j][2] * inv1);
            v1.y = __expf(oacc[m][j][3] * inv1);
            *(float2*)(o0 + 8 * j) = v0;
            *(float2*)(o1 + 8 * j) = v1;
        }
    }
}

// ============================ launch ============================
extern "C" void kernel_launch(void* const* d_in, const int* in_sizes, int n_in,
                              void* d_out, int out_size) {
    const float* Q = (const float*)d_in[0];
    const float* K = (const float*)d_in[1];
    const float* V = (const float*)d_in[2];
    const void*  M = d_in[3];
    float* out = (float*)d_out;

    prep_all<<<MASK_BLOCKS + 8192, 256>>>(M, (const float4*)K, (const float4*)V);

    cudaFuncSetAttribute(attn_kernel,
                         cudaFuncAttributeMaxDynamicSharedMemorySize, SMEM_BYTES);
    dim3 grid(SEQ / QT, BH);
    attn_kernel<<<grid, NTHR, SMEM_BYTES>>>(Q, out);
}